// round 2
// baseline (speedup 1.0000x reference)
#include <cuda_runtime.h>
#include <math.h>
#include <stdint.h>

// ---------------------------------------------------------------------------
// FrequencyAwareGatingBlock  (B=16, C=256, C2=512, H=W=64)
//
// Pipeline (after algebraic simplification):
//   f1 = LayerNorm_C(f) * gamma + beta
//   W_comb = w_poly @ diag(freq_real) @ w_expand          (precomputed per call)
//   f5 = W_comb @ f1                                      (GEMM 512x256)
//   f6 = depthwise3x3_SAME(f5)
//   g  = w_pw @ f6 ;  f7 = gelu(g)*g                      (GEMM 512x512 + act)
//   out = f + w_final @ f7                                (GEMM 256x512 + res)
// ---------------------------------------------------------------------------

#define BATCH 16
#define CIN   256
#define CEXP  512
#define HH    64
#define WW    64
#define HWSZ  4096

// scratch (device globals; no allocation allowed)
__device__ float g_f1[BATCH * CIN * HWSZ];    //  67 MB : LayerNorm output
__device__ float g_f5[BATCH * CEXP * HWSZ];   // 134 MB : comb-GEMM out, reused for f7
__device__ float g_f6[BATCH * CEXP * HWSZ];   // 134 MB : depthwise output
__device__ float g_wcomb[CEXP * CIN];         //  0.5 MB

// ---------------------------------------------------------------------------
// W_comb[o][c] = sum_k w_poly[o][k] * freq_real[k] * w_expand[k][c]
// ---------------------------------------------------------------------------
__global__ void wcomb_kernel(const float* __restrict__ w_poly,
                             const float* __restrict__ freq,
                             const float* __restrict__ w_exp,
                             float* __restrict__ wc) {
    int o = blockIdx.x;      // 0..511
    int c = threadIdx.x;     // 0..255
    float acc = 0.f;
    #pragma unroll 4
    for (int k = 0; k < CEXP; k++) {
        acc += __ldg(&w_poly[o * CEXP + k]) * __ldg(&freq[k]) *
               __ldg(&w_exp[k * CIN + c]);
    }
    wc[o * CIN + c] = acc;
}

// ---------------------------------------------------------------------------
// LayerNorm over channel dim. Block = (32 pixels, 8 channel-groups).
// ---------------------------------------------------------------------------
__global__ void ln_kernel(const float* __restrict__ f,
                          const float* __restrict__ gamma,
                          const float* __restrict__ beta,
                          float* __restrict__ out) {
    const int b  = blockIdx.y;
    const int p  = blockIdx.x * 32 + threadIdx.x;
    const int ty = threadIdx.y;                    // 0..7
    const float* fb = f + (size_t)b * CIN * HWSZ + p;

    float x[32];
    float s1 = 0.f, s2 = 0.f;
    #pragma unroll
    for (int j = 0; j < 32; j++) {
        const int c = ty + j * 8;
        const float v = fb[(size_t)c * HWSZ];
        x[j] = v;
        s1 += v;
        s2 += v * v;
    }

    __shared__ float sh1[8][32];
    __shared__ float sh2[8][32];
    __shared__ float smu[32];
    __shared__ float srs[32];
    sh1[ty][threadIdx.x] = s1;
    sh2[ty][threadIdx.x] = s2;
    __syncthreads();
    if (ty == 0) {
        float t1 = 0.f, t2 = 0.f;
        #pragma unroll
        for (int i = 0; i < 8; i++) { t1 += sh1[i][threadIdx.x]; t2 += sh2[i][threadIdx.x]; }
        const float mu  = t1 * (1.f / CIN);
        const float var = t2 * (1.f / CIN) - mu * mu;
        smu[threadIdx.x] = mu;
        srs[threadIdx.x] = rsqrtf(var + 1e-5f);
    }
    __syncthreads();
    const float mu = smu[threadIdx.x];
    const float rs = srs[threadIdx.x];

    float* ob = out + (size_t)b * CIN * HWSZ + p;
    #pragma unroll
    for (int j = 0; j < 32; j++) {
        const int c = ty + j * 8;
        ob[(size_t)c * HWSZ] = (x[j] - mu) * rs * __ldg(&gamma[c]) + __ldg(&beta[c]);
    }
}

// ---------------------------------------------------------------------------
// Depthwise 3x3 SAME. One block per (b,c) plane; plane staged in smem.
// ---------------------------------------------------------------------------
__global__ void dw_kernel(const float* __restrict__ in,
                          const float* __restrict__ w,
                          float* __restrict__ out) {
    const int plane = blockIdx.x;            // b*512 + c
    const int c     = plane & (CEXP - 1);
    const float* ip = in  + (size_t)plane * HWSZ;
    float*       op = out + (size_t)plane * HWSZ;

    __shared__ float s[HH][WW + 1];
    const int tx = threadIdx.x;              // 0..63
    const int ty = threadIdx.y;              // 0..7
    #pragma unroll
    for (int r = 0; r < 8; r++) {
        const int y = ty + r * 8;
        s[y][tx] = ip[y * WW + tx];
    }
    float wk[9];
    #pragma unroll
    for (int i = 0; i < 9; i++) wk[i] = __ldg(&w[c * 9 + i]);
    __syncthreads();

    #pragma unroll
    for (int r = 0; r < 8; r++) {
        const int y = ty + r * 8;
        float acc = 0.f;
        #pragma unroll
        for (int dy = -1; dy <= 1; dy++) {
            const int yy = y + dy;
            if (yy < 0 || yy >= HH) continue;
            #pragma unroll
            for (int dx = -1; dx <= 1; dx++) {
                const int xx = tx + dx;
                if (xx < 0 || xx >= WW) continue;
                acc += wk[(dy + 1) * 3 + (dx + 1)] * s[yy][xx];
            }
        }
        op[y * WW + tx] = acc;
    }
}

// ---------------------------------------------------------------------------
// fp32 GEMM, 128x128 tile, BK=8, 256 threads, 8x8 per thread.
//   C[b][m][n] = sum_k A[m][k] * B[b][k][n]     (+ epilogue)
// EPI: 0 = store, 1 = gelu-gate (g*gelu(g)), 2 = residual add
// ---------------------------------------------------------------------------
__device__ __forceinline__ float gelu_gate(float x) {
    return 0.5f * x * x * (1.f + erff(x * 0.70710678118654752f));
}

template <int EPI>
__global__ __launch_bounds__(256, 2)
void gemm128(const float* __restrict__ A, const float* __restrict__ Bm,
             float* __restrict__ C, const float* __restrict__ R,
             int M, int N, int K) {
    const int bz = blockIdx.z;
    Bm += (size_t)bz * K * N;
    C  += (size_t)bz * M * N;
    if (EPI == 2) R += (size_t)bz * M * N;

    const int n0 = blockIdx.x * 128;
    const int m0 = blockIdx.y * 128;

    __shared__ float As[8][128];
    __shared__ float Bs[8][128];

    const int tid  = threadIdx.x;
    const int tx   = tid & 15;
    const int ty   = tid >> 4;
    const int arow = tid >> 1;
    const int acol = (tid & 1) * 4;
    const int brow = tid >> 5;
    const int bcol = (tid & 31) * 4;

    float acc[8][8];
    #pragma unroll
    for (int i = 0; i < 8; i++)
        #pragma unroll
        for (int j = 0; j < 8; j++) acc[i][j] = 0.f;

    for (int k0 = 0; k0 < K; k0 += 8) {
        const float4 av = *(const float4*)(A  + (size_t)(m0 + arow) * K + k0 + acol);
        const float4 bv = *(const float4*)(Bm + (size_t)(k0 + brow) * N + n0 + bcol);
        As[acol + 0][arow] = av.x;
        As[acol + 1][arow] = av.y;
        As[acol + 2][arow] = av.z;
        As[acol + 3][arow] = av.w;
        *(float4*)(&Bs[brow][bcol]) = bv;
        __syncthreads();

        #pragma unroll
        for (int kk = 0; kk < 8; kk++) {
            float a[8], bb[8];
            #pragma unroll
            for (int i = 0; i < 8; i++) a[i]  = As[kk][ty * 8 + i];
            #pragma unroll
            for (int j = 0; j < 8; j++) bb[j] = Bs[kk][tx * 8 + j];
            #pragma unroll
            for (int i = 0; i < 8; i++)
                #pragma unroll
                for (int j = 0; j < 8; j++)
                    acc[i][j] += a[i] * bb[j];
        }
        __syncthreads();
    }

    #pragma unroll
    for (int i = 0; i < 8; i++) {
        const int m = m0 + ty * 8 + i;
        #pragma unroll
        for (int j = 0; j < 8; j += 4) {
            const int n = n0 + tx * 8 + j;
            float4 v = make_float4(acc[i][j], acc[i][j + 1], acc[i][j + 2], acc[i][j + 3]);
            if (EPI == 1) {
                v.x = gelu_gate(v.x); v.y = gelu_gate(v.y);
                v.z = gelu_gate(v.z); v.w = gelu_gate(v.w);
            } else if (EPI == 2) {
                const float4 r = *(const float4*)(R + (size_t)m * N + n);
                v.x += r.x; v.y += r.y; v.z += r.z; v.w += r.w;
            }
            *(float4*)(C + (size_t)m * N + n) = v;
        }
    }
}

// ---------------------------------------------------------------------------
extern "C" void kernel_launch(void* const* d_in, const int* in_sizes, int n_in,
                              void* d_out, int out_size) {
    const float* f         = (const float*)d_in[0];
    const float* ln_gamma  = (const float*)d_in[1];
    const float* ln_beta   = (const float*)d_in[2];
    const float* w_expand  = (const float*)d_in[3];
    const float* freq_real = (const float*)d_in[4];
    // d_in[5] = freq_imag : contributes nothing (Re of constant complex filter)
    const float* w_poly    = (const float*)d_in[6];
    const float* w_dw      = (const float*)d_in[7];
    const float* w_pw      = (const float*)d_in[8];
    const float* w_final   = (const float*)d_in[9];
    float* out = (float*)d_out;

    float *f1, *f5, *f6, *wcomb;
    cudaGetSymbolAddress((void**)&f1,    g_f1);
    cudaGetSymbolAddress((void**)&f5,    g_f5);
    cudaGetSymbolAddress((void**)&f6,    g_f6);
    cudaGetSymbolAddress((void**)&wcomb, g_wcomb);

    // 1) fold expand * freq_real * poly into one 512x256 matrix
    wcomb_kernel<<<CEXP, CIN>>>(w_poly, freq_real, w_expand, wcomb);

    // 2) LayerNorm over channels
    ln_kernel<<<dim3(HWSZ / 32, BATCH), dim3(32, 8)>>>(f, ln_gamma, ln_beta, f1);

    // 3) f5 = W_comb @ f1   (M=512, K=256, N=4096, per batch)
    gemm128<0><<<dim3(HWSZ / 128, CEXP / 128, BATCH), 256>>>(
        wcomb, f1, f5, nullptr, CEXP, HWSZ, CIN);

    // 4) depthwise 3x3 SAME
    dw_kernel<<<BATCH * CEXP, dim3(64, 8)>>>(f5, w_dw, f6);

    // 5) f7 = gelu_gate(w_pw @ f6)   (reuse f5 buffer)
    gemm128<1><<<dim3(HWSZ / 128, CEXP / 128, BATCH), 256>>>(
        w_pw, f6, f5, nullptr, CEXP, HWSZ, CEXP);

    // 6) out = f + w_final @ f7
    gemm128<2><<<dim3(HWSZ / 128, CIN / 128, BATCH), 256>>>(
        w_final, f5, out, f, CIN, HWSZ, CEXP);
}

// round 3
// speedup vs baseline: 2.2430x; 2.2430x over previous
#include <cuda_runtime.h>
#include <math.h>
#include <stdint.h>

// ---------------------------------------------------------------------------
// FrequencyAwareGatingBlock  (B=16, C=256, C2=512, H=W=64)
//   f1 = LayerNorm_C(f) * gamma + beta
//   W_comb = w_poly @ diag(freq_real) @ w_expand
//   f5 = W_comb @ f1            (TF32 tensor GEMM 512x256)
//   f6 = depthwise3x3_SAME(f5)
//   g  = w_pw @ f6 ; f7 = gelu(g)*g     (TF32 GEMM 512x512 + act)
//   out = f + w_final @ f7              (TF32 GEMM 256x512 + residual)
// ---------------------------------------------------------------------------

#define BATCH 16
#define CIN   256
#define CEXP  512
#define HH    64
#define WW    64
#define HWSZ  4096

__device__ float g_f1[BATCH * CIN * HWSZ];
__device__ float g_f5[BATCH * CEXP * HWSZ];
__device__ float g_f6[BATCH * CEXP * HWSZ];
__device__ float g_wcomb[CEXP * CIN];

// ---------------------------------------------------------------------------
__global__ void wcomb_kernel(const float* __restrict__ w_poly,
                             const float* __restrict__ freq,
                             const float* __restrict__ w_exp,
                             float* __restrict__ wc) {
    int o = blockIdx.x;
    int c = threadIdx.x;
    float acc = 0.f;
    #pragma unroll 4
    for (int k = 0; k < CEXP; k++) {
        acc += __ldg(&w_poly[o * CEXP + k]) * __ldg(&freq[k]) *
               __ldg(&w_exp[k * CIN + c]);
    }
    wc[o * CIN + c] = acc;
}

// ---------------------------------------------------------------------------
__global__ void ln_kernel(const float* __restrict__ f,
                          const float* __restrict__ gamma,
                          const float* __restrict__ beta,
                          float* __restrict__ out) {
    const int b  = blockIdx.y;
    const int p  = blockIdx.x * 32 + threadIdx.x;
    const int ty = threadIdx.y;
    const float* fb = f + (size_t)b * CIN * HWSZ + p;

    float x[32];
    float s1 = 0.f, s2 = 0.f;
    #pragma unroll
    for (int j = 0; j < 32; j++) {
        const int c = ty + j * 8;
        const float v = fb[(size_t)c * HWSZ];
        x[j] = v; s1 += v; s2 += v * v;
    }
    __shared__ float sh1[8][32], sh2[8][32], smu[32], srs[32];
    sh1[ty][threadIdx.x] = s1;
    sh2[ty][threadIdx.x] = s2;
    __syncthreads();
    if (ty == 0) {
        float t1 = 0.f, t2 = 0.f;
        #pragma unroll
        for (int i = 0; i < 8; i++) { t1 += sh1[i][threadIdx.x]; t2 += sh2[i][threadIdx.x]; }
        const float mu  = t1 * (1.f / CIN);
        const float var = t2 * (1.f / CIN) - mu * mu;
        smu[threadIdx.x] = mu;
        srs[threadIdx.x] = rsqrtf(var + 1e-5f);
    }
    __syncthreads();
    const float mu = smu[threadIdx.x];
    const float rs = srs[threadIdx.x];
    float* ob = out + (size_t)b * CIN * HWSZ + p;
    #pragma unroll
    for (int j = 0; j < 32; j++) {
        const int c = ty + j * 8;
        ob[(size_t)c * HWSZ] = (x[j] - mu) * rs * __ldg(&gamma[c]) + __ldg(&beta[c]);
    }
}

// ---------------------------------------------------------------------------
__global__ void dw_kernel(const float* __restrict__ in,
                          const float* __restrict__ w,
                          float* __restrict__ out) {
    const int plane = blockIdx.x;
    const int c     = plane & (CEXP - 1);
    const float* ip = in  + (size_t)plane * HWSZ;
    float*       op = out + (size_t)plane * HWSZ;

    __shared__ float s[HH][WW + 1];
    const int tx = threadIdx.x;
    const int ty = threadIdx.y;
    #pragma unroll
    for (int r = 0; r < 8; r++) s[ty + r * 8][tx] = ip[(ty + r * 8) * WW + tx];
    float wk[9];
    #pragma unroll
    for (int i = 0; i < 9; i++) wk[i] = __ldg(&w[c * 9 + i]);
    __syncthreads();

    #pragma unroll
    for (int r = 0; r < 8; r++) {
        const int y = ty + r * 8;
        float acc = 0.f;
        #pragma unroll
        for (int dy = -1; dy <= 1; dy++) {
            const int yy = y + dy;
            if (yy < 0 || yy >= HH) continue;
            #pragma unroll
            for (int dx = -1; dx <= 1; dx++) {
                const int xx = tx + dx;
                if (xx < 0 || xx >= WW) continue;
                acc += wk[(dy + 1) * 3 + (dx + 1)] * s[yy][xx];
            }
        }
        op[y * WW + tx] = acc;
    }
}

// ---------------------------------------------------------------------------
// TF32 tensor-core GEMM: C[b] = A @ B[b]   A:[M,K] row-major, B:[K,N] row-major
// 128x128 CTA tile, BK=16, 256 threads (8 warps x 64x32), m16n8k8 fragments.
// EPI: 0 = store, 1 = gelu-gate, 2 = residual add
// ---------------------------------------------------------------------------
__device__ __forceinline__ float gelu_gate(float x) {
    return 0.5f * x * x * (1.f + erff(x * 0.70710678118654752f));
}
__device__ __forceinline__ uint32_t f2tf(float x) {
    uint32_t r;
    asm("cvt.rna.tf32.f32 %0, %1;" : "=r"(r) : "f"(x));
    return r;
}
__device__ __forceinline__ void mma_tf32(float c[4], const uint32_t a[4], const uint32_t b[2]) {
    asm volatile(
        "mma.sync.aligned.m16n8k8.row.col.f32.tf32.tf32.f32 "
        "{%0,%1,%2,%3}, {%4,%5,%6,%7}, {%8,%9}, {%0,%1,%2,%3};"
        : "+f"(c[0]), "+f"(c[1]), "+f"(c[2]), "+f"(c[3])
        : "r"(a[0]), "r"(a[1]), "r"(a[2]), "r"(a[3]), "r"(b[0]), "r"(b[1]));
}

#define BK 16
#define SSTR 132   // padded smem row stride (floats)

template <int EPI>
__global__ __launch_bounds__(256, 2)
void gemm_tf32(const float* __restrict__ A, const float* __restrict__ Bm,
               float* __restrict__ C, const float* __restrict__ R,
               int M, int N, int K) {
    const int bz = blockIdx.z;
    Bm += (size_t)bz * K * N;
    C  += (size_t)bz * M * N;
    if (EPI == 2) R += (size_t)bz * M * N;

    const int n0 = blockIdx.x * 128;
    const int m0 = blockIdx.y * 128;

    __shared__ uint32_t As[BK][SSTR];   // [k][m]  (transposed)
    __shared__ uint32_t Bs[BK][SSTR];   // [k][n]

    const int tid    = threadIdx.x;
    const int wid    = tid >> 5;
    const int lane   = tid & 31;
    const int gid    = lane >> 2;     // 0..7
    const int tig    = lane & 3;      // 0..3
    const int warp_m = wid & 1;       // 2 warps along M
    const int warp_n = wid >> 1;      // 4 warps along N

    // global load indices
    const int arow = tid >> 2;          // 0..63  (+64 second pass)
    const int acol = (tid & 3) << 2;    // 0,4,8,12
    const int brow = tid >> 5;          // 0..7   (+8 second pass)
    const int bcol = (tid & 31) << 2;   // 0..124

    float acc[4][4][4];
    #pragma unroll
    for (int i = 0; i < 4; i++)
        #pragma unroll
        for (int j = 0; j < 4; j++)
            #pragma unroll
            for (int q = 0; q < 4; q++) acc[i][j][q] = 0.f;

    float4 av0, av1, bv0, bv1;
    // prologue load k0 = 0
    av0 = *(const float4*)(A  + (size_t)(m0 + arow)      * K + acol);
    av1 = *(const float4*)(A  + (size_t)(m0 + arow + 64) * K + acol);
    bv0 = *(const float4*)(Bm + (size_t)(brow)     * N + n0 + bcol);
    bv1 = *(const float4*)(Bm + (size_t)(brow + 8) * N + n0 + bcol);

    for (int k0 = 0; k0 < K; k0 += BK) {
        // stage to smem (tf32-rounded)
        As[acol + 0][arow] = f2tf(av0.x);
        As[acol + 1][arow] = f2tf(av0.y);
        As[acol + 2][arow] = f2tf(av0.z);
        As[acol + 3][arow] = f2tf(av0.w);
        As[acol + 0][arow + 64] = f2tf(av1.x);
        As[acol + 1][arow + 64] = f2tf(av1.y);
        As[acol + 2][arow + 64] = f2tf(av1.z);
        As[acol + 3][arow + 64] = f2tf(av1.w);
        {
            uint4 u0 = make_uint4(f2tf(bv0.x), f2tf(bv0.y), f2tf(bv0.z), f2tf(bv0.w));
            uint4 u1 = make_uint4(f2tf(bv1.x), f2tf(bv1.y), f2tf(bv1.z), f2tf(bv1.w));
            *(uint4*)(&Bs[brow][bcol])     = u0;
            *(uint4*)(&Bs[brow + 8][bcol]) = u1;
        }
        __syncthreads();

        // prefetch next k-tile
        if (k0 + BK < K) {
            const int kn = k0 + BK;
            av0 = *(const float4*)(A  + (size_t)(m0 + arow)      * K + kn + acol);
            av1 = *(const float4*)(A  + (size_t)(m0 + arow + 64) * K + kn + acol);
            bv0 = *(const float4*)(Bm + (size_t)(kn + brow)     * N + n0 + bcol);
            bv1 = *(const float4*)(Bm + (size_t)(kn + brow + 8) * N + n0 + bcol);
        }

        // compute 2 k8 steps
        #pragma unroll
        for (int kk = 0; kk < BK; kk += 8) {
            uint32_t afr[4][4], bfr[4][2];
            #pragma unroll
            for (int mf = 0; mf < 4; mf++) {
                const int m = warp_m * 64 + mf * 16 + gid;
                afr[mf][0] = As[kk + tig][m];
                afr[mf][1] = As[kk + tig][m + 8];
                afr[mf][2] = As[kk + tig + 4][m];
                afr[mf][3] = As[kk + tig + 4][m + 8];
            }
            #pragma unroll
            for (int nf = 0; nf < 4; nf++) {
                const int n = warp_n * 32 + nf * 8 + gid;
                bfr[nf][0] = Bs[kk + tig][n];
                bfr[nf][1] = Bs[kk + tig + 4][n];
            }
            #pragma unroll
            for (int mf = 0; mf < 4; mf++)
                #pragma unroll
                for (int nf = 0; nf < 4; nf++)
                    mma_tf32(acc[mf][nf], afr[mf], bfr[nf]);
        }
        __syncthreads();
    }

    // epilogue
    #pragma unroll
    for (int mf = 0; mf < 4; mf++) {
        #pragma unroll
        for (int nf = 0; nf < 4; nf++) {
            const int m = m0 + warp_m * 64 + mf * 16 + gid;
            const int n = n0 + warp_n * 32 + nf * 8 + tig * 2;
            float2 v0 = make_float2(acc[mf][nf][0], acc[mf][nf][1]);
            float2 v1 = make_float2(acc[mf][nf][2], acc[mf][nf][3]);
            if (EPI == 1) {
                v0.x = gelu_gate(v0.x); v0.y = gelu_gate(v0.y);
                v1.x = gelu_gate(v1.x); v1.y = gelu_gate(v1.y);
            } else if (EPI == 2) {
                const float2 r0 = *(const float2*)(R + (size_t)m * N + n);
                const float2 r1 = *(const float2*)(R + (size_t)(m + 8) * N + n);
                v0.x += r0.x; v0.y += r0.y;
                v1.x += r1.x; v1.y += r1.y;
            }
            *(float2*)(C + (size_t)m * N + n)       = v0;
            *(float2*)(C + (size_t)(m + 8) * N + n) = v1;
        }
    }
}

// ---------------------------------------------------------------------------
extern "C" void kernel_launch(void* const* d_in, const int* in_sizes, int n_in,
                              void* d_out, int out_size) {
    const float* f         = (const float*)d_in[0];
    const float* ln_gamma  = (const float*)d_in[1];
    const float* ln_beta   = (const float*)d_in[2];
    const float* w_expand  = (const float*)d_in[3];
    const float* freq_real = (const float*)d_in[4];
    // d_in[5] = freq_imag : contributes nothing
    const float* w_poly    = (const float*)d_in[6];
    const float* w_dw      = (const float*)d_in[7];
    const float* w_pw      = (const float*)d_in[8];
    const float* w_final   = (const float*)d_in[9];
    float* out = (float*)d_out;

    float *f1, *f5, *f6, *wcomb;
    cudaGetSymbolAddress((void**)&f1,    g_f1);
    cudaGetSymbolAddress((void**)&f5,    g_f5);
    cudaGetSymbolAddress((void**)&f6,    g_f6);
    cudaGetSymbolAddress((void**)&wcomb, g_wcomb);

    wcomb_kernel<<<CEXP, CIN>>>(w_poly, freq_real, w_expand, wcomb);

    ln_kernel<<<dim3(HWSZ / 32, BATCH), dim3(32, 8)>>>(f, ln_gamma, ln_beta, f1);

    // f5 = W_comb @ f1   (M=512, K=256)
    gemm_tf32<0><<<dim3(HWSZ / 128, CEXP / 128, BATCH), 256>>>(
        wcomb, f1, f5, nullptr, CEXP, HWSZ, CIN);

    dw_kernel<<<BATCH * CEXP, dim3(64, 8)>>>(f5, w_dw, f6);

    // f7 = gelu_gate(w_pw @ f6)  (reuse f5)
    gemm_tf32<1><<<dim3(HWSZ / 128, CEXP / 128, BATCH), 256>>>(
        w_pw, f6, f5, nullptr, CEXP, HWSZ, CEXP);

    // out = f + w_final @ f7
    gemm_tf32<2><<<dim3(HWSZ / 128, CIN / 128, BATCH), 256>>>(
        w_final, f5, out, f, CIN, HWSZ, CEXP);
}

// round 5
// speedup vs baseline: 2.5221x; 1.1244x over previous
#include <cuda_runtime.h>
#include <math.h>
#include <stdint.h>

// ---------------------------------------------------------------------------
// FrequencyAwareGatingBlock (B=16,C=256,C2=512,H=W=64)
// NHWC dataflow; GEMMs via tcgen05 kind::f16 with split-bf16 (hi/lo) operands
// emulating ~fp32 precision. Fallback: legacy mma.sync tf32 (plain sm_103).
//   f1 = LN(f)            NCHW -> NHWC
//   f5 = f1 @ Wcomb^T     (M=pixels, N=512, K=256)
//   f6 = dw3x3(f5)        NHWC
//   f7 = gg(f6 @ Wpw^T)   (N=512, K=512) + gelu-gate
//   out= f + f7 @ Wfin^T  (N=256, K=512), epilogue writes NCHW + residual
// ---------------------------------------------------------------------------

#define BATCH 16
#define CIN   256
#define CEXP  512
#define HH    64
#define WW    64
#define HWSZ  4096
#define MTOT  (BATCH * HWSZ)

__device__ float g_f1[(size_t)MTOT * CIN];
__device__ float g_f5[(size_t)MTOT * CEXP];
__device__ float g_f6[(size_t)MTOT * CEXP];
__device__ float g_wcomb[CEXP * CIN];

__device__ __forceinline__ float gelu_gate(float x) {
    return 0.5f * x * x * (1.f + erff(x * 0.70710678118654752f));
}

// ============================ small kernels ================================
__global__ void wcomb_kernel(const float* __restrict__ w_poly,
                             const float* __restrict__ freq,
                             const float* __restrict__ w_exp,
                             float* __restrict__ wc) {
    int o = blockIdx.x, c = threadIdx.x;
    float acc = 0.f;
    #pragma unroll 4
    for (int k = 0; k < CEXP; k++)
        acc += __ldg(&w_poly[o * CEXP + k]) * __ldg(&freq[k]) * __ldg(&w_exp[k * CIN + c]);
    wc[o * CIN + c] = acc;
}

// LayerNorm: read NCHW, write NHWC
__global__ void ln_nhwc(const float* __restrict__ f, const float* __restrict__ gamma,
                        const float* __restrict__ beta, float* __restrict__ out) {
    const int b  = blockIdx.y;
    const int p0 = blockIdx.x * 32;
    const int tx = threadIdx.x, ty = threadIdx.y;       // (32, 8)
    __shared__ float s[32][257];
    __shared__ float sh1[8][32], sh2[8][32], smu[32], srs[32];

    const float* fb = f + (size_t)b * CIN * HWSZ + p0 + tx;
    float s1 = 0.f, s2 = 0.f;
    #pragma unroll
    for (int j = 0; j < 32; j++) {
        const int c = ty + j * 8;
        const float v = fb[(size_t)c * HWSZ];
        s[tx][c] = v; s1 += v; s2 += v * v;
    }
    sh1[ty][tx] = s1; sh2[ty][tx] = s2;
    __syncthreads();
    if (ty == 0) {
        float t1 = 0.f, t2 = 0.f;
        #pragma unroll
        for (int i = 0; i < 8; i++) { t1 += sh1[i][tx]; t2 += sh2[i][tx]; }
        const float mu = t1 * (1.f / CIN);
        const float var = t2 * (1.f / CIN) - mu * mu;
        smu[tx] = mu; srs[tx] = rsqrtf(var + 1e-5f);
    }
    __syncthreads();
    const int tid = ty * 32 + tx;
    const float ga = __ldg(&gamma[tid]), be = __ldg(&beta[tid]);
    float* ob = out + ((size_t)b * HWSZ + p0) * CIN + tid;
    #pragma unroll 4
    for (int p = 0; p < 32; p++)
        ob[(size_t)p * CIN] = (s[p][tid] - smu[p]) * srs[p] * ga + be;
}

// depthwise 3x3 SAME, NHWC
__global__ void dw_nhwc(const float* __restrict__ in, const float* __restrict__ w,
                        float* __restrict__ out) {
    const int cc = blockIdx.x, y = blockIdx.y, bz = blockIdx.z;
    const int tid = threadIdx.x;
    const int c4 = cc * 32 + (tid & 31);
    const int xs = tid >> 5;
    const float4* ip = (const float4*)in + (size_t)bz * HWSZ * 128;
    float4*       op = (float4*)out + (size_t)bz * HWSZ * 128;
    const int c = c4 * 4;
    float4 wk[9];
    #pragma unroll
    for (int t = 0; t < 9; t++)
        wk[t] = make_float4(__ldg(&w[(c + 0) * 9 + t]), __ldg(&w[(c + 1) * 9 + t]),
                            __ldg(&w[(c + 2) * 9 + t]), __ldg(&w[(c + 3) * 9 + t]));
    #pragma unroll
    for (int i = 0; i < 8; i++) {
        const int x = xs + i * 8;
        float4 acc = make_float4(0.f, 0.f, 0.f, 0.f);
        #pragma unroll
        for (int dy = -1; dy <= 1; dy++) {
            const int yy = y + dy;
            if (yy < 0 || yy >= HH) continue;
            #pragma unroll
            for (int dx = -1; dx <= 1; dx++) {
                const int xx = x + dx;
                if (xx < 0 || xx >= WW) continue;
                const float4 v = ip[(size_t)(yy * WW + xx) * 128 + c4];
                const float4 wt = wk[(dy + 1) * 3 + (dx + 1)];
                acc.x += v.x * wt.x; acc.y += v.y * wt.y;
                acc.z += v.z * wt.z; acc.w += v.w * wt.w;
            }
        }
        op[(size_t)(y * WW + x) * 128 + c4] = acc;
    }
}

// ===========================================================================
// GEMM: D[128 pixels x NGEMM] = Act[128 x KTOT] * Wt[NGEMM x KTOT]^T
// EPI 0: store NHWC; 1: gelu-gate + NHWC; 2: NCHW store + residual
// ===========================================================================
#if defined(__CUDA_ARCH_FEAT_SM103_ALL) || !defined(__CUDA_ARCH__)
#define TCG_PATH 1
#endif

#if defined(__CUDA_ARCH_FEAT_SM103_ALL)
// ----------------------- tcgen05 split-bf16 path --------------------------
__device__ __forceinline__ uint32_t smem_u32(const void* p) {
    uint32_t a;
    asm("{ .reg .u64 t; cvta.to.shared.u64 t, %1; cvt.u32.u64 %0, t; }"
        : "=r"(a) : "l"(p));
    return a;
}
__device__ __forceinline__ uint32_t elect1() {
    uint32_t p;
    asm volatile("{ .reg .pred p; elect.sync _|p, 0xFFFFFFFF; selp.b32 %0,1,0,p; }"
                 : "=r"(p));
    return p;
}
#define TCG_ALLOC(sm_addr, ncols) \
    asm volatile("tcgen05.alloc.cta_group::1.sync.aligned.shared::cta.b32 [%0], %1;" \
                 :: "r"(sm_addr), "r"(ncols) : "memory")
#define TCG_DEALLOC(tmem, ncols) \
    asm volatile("tcgen05.dealloc.cta_group::1.sync.aligned.b32 %0, %1;" \
                 :: "r"(tmem), "r"(ncols))
#define TCG_RELINQ() \
    asm volatile("tcgen05.relinquish_alloc_permit.cta_group::1.sync.aligned;")
#define TCG_COMMIT(mbar) \
    asm volatile("tcgen05.commit.cta_group::1.mbarrier::arrive::one.shared::cluster.b64 [%0];" \
                 :: "r"(mbar) : "memory")
#define TCG_WAIT_LD() asm volatile("tcgen05.wait::ld.sync.aligned;" ::: "memory")
#define TCG_FENCE_AFTER() asm volatile("tcgen05.fence::after_thread_sync;" ::: "memory")
#define MBAR_INIT(mbar, cnt) \
    asm volatile("mbarrier.init.shared.b64 [%0], %1;" :: "r"(mbar), "r"(cnt) : "memory")
#define MBAR_WAIT(mbar_a, par) do {                                              \
    uint32_t _m = (mbar_a); uint32_t _p = (par); uint32_t _d;                    \
    asm volatile("{ .reg .pred p;"                                               \
        " mbarrier.try_wait.parity.acquire.cta.shared::cta.b64 p, [%1], %2;"     \
        " selp.b32 %0,1,0,p; }" : "=r"(_d) : "r"(_m), "r"(_p) : "memory");       \
    if (!_d) {                                                                   \
        asm volatile("{ .reg .pred P1; WL_%=:"                                   \
            " mbarrier.try_wait.parity.acquire.cta.shared::cta.b64 P1, [%0], %1, 0x989680;" \
            " @P1 bra.uni WD_%=; bra.uni WL_%=; WD_%=: }"                        \
            :: "r"(_m), "r"(_p) : "memory");                                     \
    }                                                                            \
} while (0)
#define LDTM_X32(r, tmem_addr) \
    asm volatile("tcgen05.ld.sync.aligned.32x32b.x32.b32 " \
        "{%0,%1,%2,%3,%4,%5,%6,%7,%8,%9,%10,%11,%12,%13,%14,%15," \
        "%16,%17,%18,%19,%20,%21,%22,%23,%24,%25,%26,%27,%28,%29,%30,%31}, [%32];" \
        : "=r"((r)[0]),"=r"((r)[1]),"=r"((r)[2]),"=r"((r)[3]), \
          "=r"((r)[4]),"=r"((r)[5]),"=r"((r)[6]),"=r"((r)[7]), \
          "=r"((r)[8]),"=r"((r)[9]),"=r"((r)[10]),"=r"((r)[11]), \
          "=r"((r)[12]),"=r"((r)[13]),"=r"((r)[14]),"=r"((r)[15]), \
          "=r"((r)[16]),"=r"((r)[17]),"=r"((r)[18]),"=r"((r)[19]), \
          "=r"((r)[20]),"=r"((r)[21]),"=r"((r)[22]),"=r"((r)[23]), \
          "=r"((r)[24]),"=r"((r)[25]),"=r"((r)[26]),"=r"((r)[27]), \
          "=r"((r)[28]),"=r"((r)[29]),"=r"((r)[30]),"=r"((r)[31]) \
        : "r"(tmem_addr))

static constexpr uint64_t DESC_BASE_SW128 =
    (uint64_t(2) << 61) | (uint64_t(1) << 46) | (uint64_t(64) << 32) | (uint64_t(1) << 16);
__device__ __forceinline__ uint64_t mk_desc(uint32_t addr) {
    return DESC_BASE_SW128 | ((uint64_t)(addr >> 4) & 0x3FFF);
}
// tcgen05.mma kind::f16 (bf16 in / fp32 accum), SS form, cg1
__device__ __forceinline__ void mma_bf16_ss(uint32_t d, uint64_t ad, uint64_t bd,
                                            uint32_t idesc, uint32_t en) {
    asm volatile(
        "{ .reg .pred p; setp.ne.u32 p, %4, 0;\n\t"
        "tcgen05.mma.cta_group::1.kind::f16 [%0], %1, %2, %3, {%5,%5,%5,%5}, p; }\n"
        :: "r"(d), "l"(ad), "l"(bd), "r"(idesc), "r"(en), "r"(0u) : "memory");
}
// split fp32x4 into packed bf16 hi / lo pairs (memory order x,y / z,w)
__device__ __forceinline__ void split4(float4 v, uint2& hi, uint2& lo) {
    uint32_t h01, h23, l01, l23;
    asm("cvt.rn.bf16x2.f32 %0, %1, %2;" : "=r"(h01) : "f"(v.y), "f"(v.x));
    asm("cvt.rn.bf16x2.f32 %0, %1, %2;" : "=r"(h23) : "f"(v.w), "f"(v.z));
    float r0 = v.x - __uint_as_float(h01 << 16);
    float r1 = v.y - __uint_as_float(h01 & 0xFFFF0000u);
    float r2 = v.z - __uint_as_float(h23 << 16);
    float r3 = v.w - __uint_as_float(h23 & 0xFFFF0000u);
    asm("cvt.rn.bf16x2.f32 %0, %1, %2;" : "=r"(l01) : "f"(r1), "f"(r0));
    asm("cvt.rn.bf16x2.f32 %0, %1, %2;" : "=r"(l23) : "f"(r3), "f"(r2));
    hi = make_uint2(h01, h23);
    lo = make_uint2(l01, l23);
}

template <int NGEMM, int KTOT, int EPI>
__global__ __launch_bounds__(256, 1)
void gemm_tc(const float* __restrict__ Act, const float* __restrict__ Wt,
             float* __restrict__ Out, const float* __restrict__ Res) {
    extern __shared__ char sm[];
    const int tid = threadIdx.x, wid = tid >> 5, lane = tid & 31;
    const int m0 = blockIdx.x * 128;
    const uint32_t sbase = smem_u32(sm);
    const uint32_t tilesAbs = (sbase + 32 + 1023) & ~1023u;
    const uint32_t trel = tilesAbs - sbase;
    // per-stage: A' 128 rows x 128B (hi|lo bf16), B' NGEMM rows x 128B
    constexpr uint32_t ABYTES = 128 * 128;
    constexpr uint32_t BBYTES = (uint32_t)NGEMM * 128;
    constexpr uint32_t BUF = ABYTES + BBYTES;
    const uint32_t mbar = sbase + 8;

    if (wid == 0) TCG_ALLOC(sbase, 512);
    if (tid == 0) { MBAR_INIT(mbar, 1); MBAR_INIT(mbar + 8, 1); }
    __syncthreads();
    uint32_t tbase;
    asm volatile("ld.shared.b32 %0, [%1];" : "=r"(tbase) : "r"(sbase));

    // idesc kind::f16: dtype f32, a/b bf16, N=256 per MMA, M=128
    constexpr uint32_t IDESC =
        (1u << 4) | (1u << 7) | (1u << 10) | ((256u / 8) << 17) | ((128u / 16) << 24);
    constexpr int NC = KTOT / 32;      // K chunks of 32 fp32
    constexpr int NH = NGEMM / 256;    // MMA halves along N

    int ph0 = 0, ph1 = 0;
    for (int ch = 0; ch < NC; ch++) {
        const int bsel = ch & 1;
        if (ch >= 2) {
            if (bsel == 0) { MBAR_WAIT(mbar, ph0); ph0 ^= 1; }
            else           { MBAR_WAIT(mbar + 8, ph1); ph1 ^= 1; }
        }
        const uint32_t aOff = trel + bsel * BUF;
        const uint32_t bOff = aOff + ABYTES;
        const int kc = ch * 32;
        // A': 128 rows x 32 fp32 -> [hi(64B) | lo(64B)] per row
        #pragma unroll
        for (int t = 0; t < 4; t++) {
            const int i = tid + t * 256, row = i >> 3, c4 = i & 7;
            const float4 v = *(const float4*)(Act + (size_t)(m0 + row) * KTOT + kc + c4 * 4);
            uint2 hi, lo; split4(v, hi, lo);
            uint32_t bh = row * 128 + c4 * 8;
            uint32_t bl = bh + 64;
            *(uint2*)(sm + aOff + (bh ^ ((bh >> 3) & 0x70))) = hi;
            *(uint2*)(sm + aOff + (bl ^ ((bl >> 3) & 0x70))) = lo;
        }
        // B': NGEMM rows x 32 fp32 -> hi|lo
        #pragma unroll 4
        for (int t = 0; t < NGEMM / 32; t++) {
            const int i = tid + t * 256, row = i >> 3, c4 = i & 7;
            const float4 v = *(const float4*)(Wt + (size_t)row * KTOT + kc + c4 * 4);
            uint2 hi, lo; split4(v, hi, lo);
            uint32_t bh = row * 128 + c4 * 8;
            uint32_t bl = bh + 64;
            *(uint2*)(sm + bOff + (bh ^ ((bh >> 3) & 0x70))) = hi;
            *(uint2*)(sm + bOff + (bl ^ ((bl >> 3) & 0x70))) = lo;
        }
        __syncthreads();
        if (wid == 0 && elect1()) {
            asm volatile("fence.proxy.async.shared::cta;" ::: "memory");
            const uint64_t ad = mk_desc(sbase + aOff);
            const uint64_t bd0 = mk_desc(sbase + bOff);
            #pragma unroll
            for (int h = 0; h < NH; h++) {
                const uint32_t dt = tbase + h * 256;
                const uint64_t bd = bd0 + h * 2048;   // +256 rows * 128B / 16
                // hi*hi (k16 x2), hi*lo, lo*hi  — desc units: 16B; k16 = +2, lo half = +4
                mma_bf16_ss(dt, ad + 0, bd + 0, IDESC, (ch > 0) ? 1u : 0u);
                mma_bf16_ss(dt, ad + 2, bd + 2, IDESC, 1u);
                mma_bf16_ss(dt, ad + 0, bd + 4, IDESC, 1u);
                mma_bf16_ss(dt, ad + 2, bd + 6, IDESC, 1u);
                mma_bf16_ss(dt, ad + 4, bd + 0, IDESC, 1u);
                mma_bf16_ss(dt, ad + 6, bd + 2, IDESC, 1u);
            }
            TCG_COMMIT(bsel ? (mbar + 8) : mbar);
        }
    }
    {
        const int bsel = (NC - 1) & 1;
        if (bsel == 0) MBAR_WAIT(mbar, ph0); else MBAR_WAIT(mbar + 8, ph1);
    }
    TCG_FENCE_AFTER();
    __syncthreads();   // tiles free for epilogue scratch

    const int wr = wid & 3, half = wid >> 2;
    const int rbase = wr * 32;
    if (EPI < 2) {
        float* pat = (float*)(sm + trel) + wid * (32 * 33);
        constexpr int CH = NGEMM / 64;
        for (int j = 0; j < CH; j++) {
            const int c0 = half * (NGEMM / 2) + j * 32;
            uint32_t r[32];
            LDTM_X32(r, tbase + c0);
            TCG_WAIT_LD();
            #pragma unroll
            for (int q = 0; q < 32; q++) {
                const float x = __uint_as_float(r[q]);
                pat[lane * 33 + q] = (EPI == 1) ? gelu_gate(x) : x;
            }
            __syncwarp();
            #pragma unroll
            for (int g = 0; g < 8; g++) {
                const int pp = g * 4 + (lane >> 3), qq = (lane & 7) * 4;
                float4 v = make_float4(pat[pp * 33 + qq],     pat[pp * 33 + qq + 1],
                                       pat[pp * 33 + qq + 2], pat[pp * 33 + qq + 3]);
                *(float4*)(Out + (size_t)(m0 + rbase + pp) * NGEMM + c0 + qq) = v;
            }
            __syncwarp();
        }
    } else {
        const int b = m0 >> 12, p0 = m0 & 4095;
        for (int j = 0; j < 4; j++) {
            const int c0 = half * 128 + j * 32;
            uint32_t r[32];
            LDTM_X32(r, tbase + c0);
            TCG_WAIT_LD();
            #pragma unroll
            for (int q = 0; q < 32; q++) {
                const size_t idx =
                    ((size_t)b * NGEMM + c0 + q) * HWSZ + p0 + rbase + lane;
                Out[idx] = __uint_as_float(r[q]) + Res[idx];
            }
        }
    }
    __syncthreads();
    if (wid == 0) { TCG_RELINQ(); TCG_DEALLOC(tbase, 512); }
}

#else
// ------------------- fallback: legacy mma.sync tf32 path -------------------
__device__ __forceinline__ uint32_t f2tf(float x) {
    uint32_t r;
    asm("cvt.rna.tf32.f32 %0, %1;" : "=r"(r) : "f"(x));
    return r;
}
__device__ __forceinline__ void mma_tf32(float c[4], const uint32_t a[4], const uint32_t b[2]) {
    asm volatile(
        "mma.sync.aligned.m16n8k8.row.col.f32.tf32.tf32.f32 "
        "{%0,%1,%2,%3}, {%4,%5,%6,%7}, {%8,%9}, {%0,%1,%2,%3};"
        : "+f"(c[0]), "+f"(c[1]), "+f"(c[2]), "+f"(c[3])
        : "r"(a[0]), "r"(a[1]), "r"(a[2]), "r"(a[3]), "r"(b[0]), "r"(b[1]));
}

template <int NGEMM, int KTOT, int EPI>
__global__ __launch_bounds__(256, 1)
void gemm_tc(const float* __restrict__ Act, const float* __restrict__ Wt,
             float* __restrict__ Out, const float* __restrict__ Res) {
    extern __shared__ char smraw[];
    uint32_t (*As)[132] = (uint32_t(*)[132])smraw;                 // [16][132] k-major->m
    uint32_t (*Bs)[132] = (uint32_t(*)[132])(smraw + 16 * 132 * 4);
    const int tid = threadIdx.x, wid = tid >> 5, lane = tid & 31;
    const int gid = lane >> 2, tig = lane & 3;
    const int warp_m = wid & 1, warp_n = wid >> 1;
    const int m0 = blockIdx.x * 128;
    const int grow = tid >> 2, gcol = (tid & 3) * 4;

    for (int nc = 0; nc < NGEMM / 128; nc++) {
        float acc[4][4][4];
        #pragma unroll
        for (int i = 0; i < 4; i++)
            #pragma unroll
            for (int j = 0; j < 4; j++)
                #pragma unroll
                for (int q = 0; q < 4; q++) acc[i][j][q] = 0.f;

        for (int k0 = 0; k0 < KTOT; k0 += 16) {
            const float4 av0 = *(const float4*)(Act + (size_t)(m0 + grow) * KTOT + k0 + gcol);
            const float4 av1 = *(const float4*)(Act + (size_t)(m0 + grow + 64) * KTOT + k0 + gcol);
            const float4 bv0 = *(const float4*)(Wt + (size_t)(nc * 128 + grow) * KTOT + k0 + gcol);
            const float4 bv1 = *(const float4*)(Wt + (size_t)(nc * 128 + grow + 64) * KTOT + k0 + gcol);
            __syncthreads();
            As[gcol + 0][grow] = f2tf(av0.x); As[gcol + 1][grow] = f2tf(av0.y);
            As[gcol + 2][grow] = f2tf(av0.z); As[gcol + 3][grow] = f2tf(av0.w);
            As[gcol + 0][grow + 64] = f2tf(av1.x); As[gcol + 1][grow + 64] = f2tf(av1.y);
            As[gcol + 2][grow + 64] = f2tf(av1.z); As[gcol + 3][grow + 64] = f2tf(av1.w);
            Bs[gcol + 0][grow] = f2tf(bv0.x); Bs[gcol + 1][grow] = f2tf(bv0.y);
            Bs[gcol + 2][grow] = f2tf(bv0.z); Bs[gcol + 3][grow] = f2tf(bv0.w);
            Bs[gcol + 0][grow + 64] = f2tf(bv1.x); Bs[gcol + 1][grow + 64] = f2tf(bv1.y);
            Bs[gcol + 2][grow + 64] = f2tf(bv1.z); Bs[gcol + 3][grow + 64] = f2tf(bv1.w);
            __syncthreads();
            #pragma unroll
            for (int kk = 0; kk < 16; kk += 8) {
                uint32_t afr[4][4], bfr[4][2];
                #pragma unroll
                for (int mf = 0; mf < 4; mf++) {
                    const int m = warp_m * 64 + mf * 16 + gid;
                    afr[mf][0] = As[kk + tig][m];
                    afr[mf][1] = As[kk + tig][m + 8];
                    afr[mf][2] = As[kk + tig + 4][m];
                    afr[mf][3] = As[kk + tig + 4][m + 8];
                }
                #pragma unroll
                for (int nf = 0; nf < 4; nf++) {
                    const int n = warp_n * 32 + nf * 8 + gid;
                    bfr[nf][0] = Bs[kk + tig][n];
                    bfr[nf][1] = Bs[kk + tig + 4][n];
                }
                #pragma unroll
                for (int mf = 0; mf < 4; mf++)
                    #pragma unroll
                    for (int nf = 0; nf < 4; nf++)
                        mma_tf32(acc[mf][nf], afr[mf], bfr[nf]);
            }
        }
        // epilogue for this n-chunk
        #pragma unroll
        for (int mf = 0; mf < 4; mf++) {
            #pragma unroll
            for (int nf = 0; nf < 4; nf++) {
                const int mrow = warp_m * 64 + mf * 16 + gid;
                const int n = nc * 128 + warp_n * 32 + nf * 8 + tig * 2;
                float2 v0 = make_float2(acc[mf][nf][0], acc[mf][nf][1]);
                float2 v1 = make_float2(acc[mf][nf][2], acc[mf][nf][3]);
                if (EPI == 1) {
                    v0.x = gelu_gate(v0.x); v0.y = gelu_gate(v0.y);
                    v1.x = gelu_gate(v1.x); v1.y = gelu_gate(v1.y);
                }
                if (EPI < 2) {
                    *(float2*)(Out + (size_t)(m0 + mrow) * NGEMM + n)     = v0;
                    *(float2*)(Out + (size_t)(m0 + mrow + 8) * NGEMM + n) = v1;
                } else {
                    const int b = m0 >> 12, p0 = m0 & 4095;
                    const size_t i00 = ((size_t)b * NGEMM + n)     * HWSZ + p0 + mrow;
                    const size_t i01 = ((size_t)b * NGEMM + n + 1) * HWSZ + p0 + mrow;
                    Out[i00]     = v0.x + Res[i00];
                    Out[i01]     = v0.y + Res[i01];
                    Out[i00 + 8] = v1.x + Res[i00 + 8];
                    Out[i01 + 8] = v1.y + Res[i01 + 8];
                }
            }
        }
        __syncthreads();
    }
}
#endif

// ============================ launcher =====================================
extern "C" void kernel_launch(void* const* d_in, const int* in_sizes, int n_in,
                              void* d_out, int out_size) {
    const float* f         = (const float*)d_in[0];
    const float* ln_gamma  = (const float*)d_in[1];
    const float* ln_beta   = (const float*)d_in[2];
    const float* w_expand  = (const float*)d_in[3];
    const float* freq_real = (const float*)d_in[4];
    // d_in[5] = freq_imag: contributes nothing (constant real filter)
    const float* w_poly    = (const float*)d_in[6];
    const float* w_dw      = (const float*)d_in[7];
    const float* w_pw      = (const float*)d_in[8];
    const float* w_final   = (const float*)d_in[9];
    float* out = (float*)d_out;

    float *f1, *f5, *f6, *wcomb;
    cudaGetSymbolAddress((void**)&f1,    g_f1);
    cudaGetSymbolAddress((void**)&f5,    g_f5);
    cudaGetSymbolAddress((void**)&f6,    g_f6);
    cudaGetSymbolAddress((void**)&wcomb, g_wcomb);

    const int SM512 = 2048 + 2 * (16384 + 512 * 128);   // 165888
    const int SM256 = 2048 + 2 * (16384 + 256 * 128);   // 100352
    cudaFuncSetAttribute(gemm_tc<512, 256, 0>,
                         cudaFuncAttributeMaxDynamicSharedMemorySize, SM512);
    cudaFuncSetAttribute(gemm_tc<512, 512, 1>,
                         cudaFuncAttributeMaxDynamicSharedMemorySize, SM512);
    cudaFuncSetAttribute(gemm_tc<256, 512, 2>,
                         cudaFuncAttributeMaxDynamicSharedMemorySize, SM256);

    wcomb_kernel<<<CEXP, CIN>>>(w_poly, freq_real, w_expand, wcomb);
    ln_nhwc<<<dim3(HWSZ / 32, BATCH), dim3(32, 8)>>>(f, ln_gamma, ln_beta, f1);

    gemm_tc<512, 256, 0><<<MTOT / 128, 256, SM512>>>(f1, wcomb, f5, nullptr);
    dw_nhwc<<<dim3(4, HH, BATCH), 256>>>(f5, w_dw, f6);
    gemm_tc<512, 512, 1><<<MTOT / 128, 256, SM512>>>(f6, w_pw, f5, nullptr);
    gemm_tc<256, 512, 2><<<MTOT / 128, 256, SM256>>>(f5, w_final, out, f);
}